// round 15
// baseline (speedup 1.0000x reference)
#include <cuda_runtime.h>
#include <cuda_bf16.h>
#include <cstdint>
#include <math.h>

#define B_ 4
#define L_ 256
#define D_ 512
#define H_ 8
#define DK_ 64

typedef __nv_bfloat16 bf16;
typedef __nv_bfloat162 bf162;

// ---------------------------------------------------------------------------
// Scratch (allocation-free rule: __device__ globals)
// ---------------------------------------------------------------------------
__device__ float g_qh[B_*H_*L_*DK_];
__device__ float g_kh[B_*H_*L_*DK_];
__device__ float g_rsum4[B_*H_*4*L_];               // per-jblock row partial sums

__device__ __align__(16) bf16 g_Ehi[B_*H_*L_*L_];   // exp(scores) hi
__device__ __align__(16) bf16 g_Elo[B_*H_*L_*L_];   // exp(scores) lo
__device__ __align__(16) bf16 g_VThi[B_*H_*DK_*L_]; // V^T [bh][dk][j]
__device__ __align__(16) bf16 g_VTlo[B_*H_*DK_*L_];

__device__ __align__(16) bf16 g_Whi[4*512*512];    // Wq,Wk,Wv,W0 TRANSPOSED [n][k]
__device__ __align__(16) bf16 g_Wlo[4*512*512];
__device__ __align__(16) bf16 g_ctx_hi[1024*512];  // attention context [m][k]
__device__ __align__(16) bf16 g_ctx_lo[1024*512];

// ---------------------------------------------------------------------------
__device__ __forceinline__ uint32_t smem_u32(const void* p) {
    uint32_t a;
    asm("{ .reg .u64 t; cvta.to.shared.u64 t, %1; cvt.u32.u64 %0, t; }" : "=r"(a) : "l"(p));
    return a;
}
__device__ __forceinline__ float tanh_fast(float x) {
    float y;
    asm("tanh.approx.f32 %0, %1;" : "=f"(y) : "f"(x));
    return y;
}
__device__ __forceinline__ void ldm_x4(uint32_t* r, uint32_t addr) {
    asm volatile("ldmatrix.sync.aligned.m8n8.x4.shared.b16 {%0,%1,%2,%3}, [%4];"
        : "=r"(r[0]), "=r"(r[1]), "=r"(r[2]), "=r"(r[3]) : "r"(addr));
}
__device__ __forceinline__ void mma_bf16(float* c, const uint32_t* a, const uint32_t* b) {
    asm volatile(
        "mma.sync.aligned.m16n8k16.row.col.f32.bf16.bf16.f32 "
        "{%0,%1,%2,%3}, {%4,%5,%6,%7}, {%8,%9}, {%0,%1,%2,%3};"
        : "+f"(c[0]), "+f"(c[1]), "+f"(c[2]), "+f"(c[3])
        : "r"(a[0]), "r"(a[1]), "r"(a[2]), "r"(a[3]), "r"(b[0]), "r"(b[1]));
}
__device__ __forceinline__ void split_bf(float x, bf16& hi, bf16& lo) {
    hi = __float2bfloat16_rn(x);
    lo = __float2bfloat16_rn(x - __bfloat162float(hi));
}
__device__ __forceinline__ void split2u(float a, float b, uint32_t& h, uint32_t& l) {
    bf16 ha, la, hb, lb;
    split_bf(a, ha, la);
    split_bf(b, hb, lb);
    bf162 hh(ha, hb), ll(la, lb);
    h = *(uint32_t*)&hh;
    l = *(uint32_t*)&ll;
}

// ---------------------------------------------------------------------------
// W [k][n] -> [n][k] transpose + hi/lo split.  block (32,8), grid (16,16,4)
// ---------------------------------------------------------------------------
__global__ __launch_bounds__(256) void convert_w_kernel(
    const float* __restrict__ Wq, const float* __restrict__ Wk,
    const float* __restrict__ Wv, const float* __restrict__ W0)
{
    __shared__ float tile[32][33];
    int z = blockIdx.z;
    const float* W = (z == 0) ? Wq : (z == 1 ? Wk : (z == 2 ? Wv : W0));
    int k0 = blockIdx.x * 32, n0 = blockIdx.y * 32;
    int tx = threadIdx.x, ty = threadIdx.y;
    #pragma unroll
    for (int it = 0; it < 4; it++)
        tile[ty + it * 8][tx] = W[(size_t)(k0 + ty + it * 8) * D_ + n0 + tx];
    __syncthreads();
    size_t zb = (size_t)z * (512*512);
    #pragma unroll
    for (int it = 0; it < 4; it++) {
        int nr = ty + it * 8;
        bf16 hi, lo;
        split_bf(tile[tx][nr], hi, lo);
        g_Whi[zb + (size_t)(n0 + nr) * D_ + k0 + tx] = hi;
        g_Wlo[zb + (size_t)(n0 + nr) * D_ + k0 + tx] = lo;
    }
}

// ---------------------------------------------------------------------------
// 3xBF16 tensor-core GEMM, templated tile width.
//   NT        : N tile (64 or 128)
//   HEADSPLIT : head-split output handling in epilogue
//   AFP32     : A read as fp32 and split in registers (fuses input conversion)
// Runtime vt flag (HEADSPLIT only): write V^T bf16 hi/lo instead of fp32.
// ---------------------------------------------------------------------------
#define SA 40
#define A_HALVES (128*SA)

constexpr int gemm_smem_b(int nt) {
    return 2 * (2 * A_HALVES + 2 * nt * SA) * 2;
}

template<int NT, bool HEADSPLIT, bool AFP32>
__device__ __forceinline__ void gemm_core(
    const float* __restrict__ Af_g,
    const bf16* __restrict__ Ahi_g, const bf16* __restrict__ Alo_g,
    const bf16* __restrict__ Bhi_g, const bf16* __restrict__ Blo_g,
    const float* __restrict__ bias, float* __restrict__ Y, bool vt)
{
    constexpr int NTILES = NT / 16;
    constexpr int NB = NTILES / 2;
    constexpr int B_HALVES_T = NT * SA;
    constexpr int BUF_H = 2 * A_HALVES + 2 * B_HALVES_T;
    constexpr int TPRB = 256 / NT;
    constexpr int BPT = NT / 64;

    extern __shared__ __align__(16) bf16 smh[];
    const int tid = threadIdx.x;
    const int lane = tid & 31, wid = tid >> 5;
    const int g = lane >> 2, t4 = lane & 3;
    const int warp_m = (wid & 3) * 32;
    const int warp_n = (wid >> 2) * (NT / 2);
    const int m0 = blockIdx.x * 128, n0 = blockIdx.y * NT;

    const int am = tid >> 1, ahh = (tid & 1) * 16;
    const int bn = tid / TPRB, bo = (tid % TPRB) * (32 / TPRB);

    const float* Af = Af_g ? Af_g + (size_t)(m0 + am) * D_ + ahh : (const float*)0;
    const bf16* Ash = Ahi_g ? Ahi_g + (size_t)(m0 + am) * D_ + ahh : (const bf16*)0;
    const bf16* Asl = Alo_g ? Alo_g + (size_t)(m0 + am) * D_ + ahh : (const bf16*)0;
    const bf16* Bsh = Bhi_g + (size_t)(n0 + bn) * D_ + bo;
    const bf16* Bsl = Blo_g + (size_t)(n0 + bn) * D_ + bo;

    float acc[2][NTILES][4];
    #pragma unroll
    for (int i = 0; i < 2; i++)
        #pragma unroll
        for (int j = 0; j < NTILES; j++)
            #pragma unroll
            for (int c = 0; c < 4; c++) acc[i][j][c] = 0.0f;

    const int lrow = lane & 15;
    const int lk   = (lane >> 4) * 8;
    const int bln  = lane & 7;
    const int bseg = (lane >> 3) & 1;
    const int bhi16 = (lane >> 4);
    const uint32_t smem_base = smem_u32(smh);
    const uint32_t aoff0 = ((warp_m + lrow)      * SA + lk) * 2;
    const uint32_t aoff1 = ((warp_m + 16 + lrow) * SA + lk) * 2;
    uint32_t boffs[NB];
    #pragma unroll
    for (int t = 0; t < NB; t++)
        boffs[t] = ((warp_n + t * 16 + bln) * SA + bseg * 8) * 2 + bhi16 * (8 * SA * 2);

    float4 rAf[4];
    uint4 rA_h[2], rA_l[2];
    uint4 rB_h[BPT], rB_l[BPT];

    if (AFP32) {
        #pragma unroll
        for (int u = 0; u < 4; u++) rAf[u] = *(const float4*)(Af + u * 4);
    } else {
        rA_h[0] = *(const uint4*)(Ash);     rA_h[1] = *(const uint4*)(Ash + 8);
        rA_l[0] = *(const uint4*)(Asl);     rA_l[1] = *(const uint4*)(Asl + 8);
    }
    #pragma unroll
    for (int p = 0; p < BPT; p++) {
        rB_h[p] = *(const uint4*)(Bsh + p * 8);
        rB_l[p] = *(const uint4*)(Bsl + p * 8);
    }

    for (int s = 0; s < 16; s++) {
        const int buf = s & 1;
        bf16* Ah_s = smh + buf * BUF_H;
        bf16* Al_s = Ah_s + A_HALVES;
        bf16* Bh_s = Al_s + A_HALVES;
        bf16* Bl_s = Bh_s + B_HALVES_T;

        if (AFP32) {
            uint32_t h[8], l[8];
            #pragma unroll
            for (int u = 0; u < 4; u++) {
                split2u(rAf[u].x, rAf[u].y, h[2 * u],     l[2 * u]);
                split2u(rAf[u].z, rAf[u].w, h[2 * u + 1], l[2 * u + 1]);
            }
            *(uint4*)&Ah_s[am * SA + ahh]     = make_uint4(h[0], h[1], h[2], h[3]);
            *(uint4*)&Ah_s[am * SA + ahh + 8] = make_uint4(h[4], h[5], h[6], h[7]);
            *(uint4*)&Al_s[am * SA + ahh]     = make_uint4(l[0], l[1], l[2], l[3]);
            *(uint4*)&Al_s[am * SA + ahh + 8] = make_uint4(l[4], l[5], l[6], l[7]);
        } else {
            *(uint4*)&Ah_s[am * SA + ahh]     = rA_h[0];
            *(uint4*)&Ah_s[am * SA + ahh + 8] = rA_h[1];
            *(uint4*)&Al_s[am * SA + ahh]     = rA_l[0];
            *(uint4*)&Al_s[am * SA + ahh + 8] = rA_l[1];
        }
        #pragma unroll
        for (int p = 0; p < BPT; p++) {
            *(uint4*)&Bh_s[bn * SA + bo + p * 8] = rB_h[p];
            *(uint4*)&Bl_s[bn * SA + bo + p * 8] = rB_l[p];
        }
        __syncthreads();

        if (s < 15) {
            const int off = (s + 1) * 32;
            if (AFP32) {
                #pragma unroll
                for (int u = 0; u < 4; u++) rAf[u] = *(const float4*)(Af + off + u * 4);
            } else {
                rA_h[0] = *(const uint4*)(Ash + off); rA_h[1] = *(const uint4*)(Ash + off + 8);
                rA_l[0] = *(const uint4*)(Asl + off); rA_l[1] = *(const uint4*)(Asl + off + 8);
            }
            #pragma unroll
            for (int p = 0; p < BPT; p++) {
                rB_h[p] = *(const uint4*)(Bsh + off + p * 8);
                rB_l[p] = *(const uint4*)(Bsl + off + p * 8);
            }
        }

        const uint32_t base = smem_base + (uint32_t)(buf * BUF_H * 2);
        const uint32_t aBh = base;
        const uint32_t aBl = base + A_HALVES * 2;
        const uint32_t bBh = base + 2 * A_HALVES * 2;
        const uint32_t bBl = bBh + B_HALVES_T * 2;

        #pragma unroll
        for (int kk = 0; kk < 2; kk++) {
            const uint32_t ko = kk * 32;
            uint32_t Ah0[4], Ah1[4], Al0[4], Al1[4];
            uint32_t Bh[NB][4], Bl[NB][4];
            ldm_x4(Ah0, aBh + aoff0 + ko);
            ldm_x4(Ah1, aBh + aoff1 + ko);
            ldm_x4(Al0, aBl + aoff0 + ko);
            ldm_x4(Al1, aBl + aoff1 + ko);
            #pragma unroll
            for (int t = 0; t < NB; t++) {
                ldm_x4(Bh[t], bBh + boffs[t] + ko);
                ldm_x4(Bl[t], bBl + boffs[t] + ko);
            }

            #pragma unroll
            for (int i = 0; i < 2; i++) {
                uint32_t* ahp = i ? Ah1 : Ah0;
                uint32_t* alp = i ? Al1 : Al0;
                #pragma unroll
                for (int j = 0; j < NTILES; j++) {
                    uint32_t* bhp = Bh[j >> 1];
                    uint32_t* blp = Bl[j >> 1];
                    uint32_t bhf[2] = { bhp[(j & 1) * 2], bhp[(j & 1) * 2 + 1] };
                    uint32_t blf[2] = { blp[(j & 1) * 2], blp[(j & 1) * 2 + 1] };
                    mma_bf16(acc[i][j], ahp, bhf);
                    mma_bf16(acc[i][j], ahp, blf);
                    mma_bf16(acc[i][j], alp, bhf);
                }
            }
        }
    }

    #pragma unroll
    for (int i = 0; i < 2; i++) {
        #pragma unroll
        for (int j = 0; j < NTILES; j++) {
            int col_loc = warp_n + (j >> 1) * 16 + (j & 1) * 8 + 2 * t4;
            int cng = n0 + col_loc;
            float b0 = bias[cng], b1 = bias[cng + 1];
            int r0 = m0 + warp_m + i * 16 + g;
            int r1 = r0 + 8;
            float2 v0 = make_float2(acc[i][j][0] + b0, acc[i][j][1] + b1);
            float2 v1 = make_float2(acc[i][j][2] + b0, acc[i][j][3] + b1);
            if (HEADSPLIT) {
                int h = cng >> 6, dk = cng & 63;
                if (vt) {
                    // V path: write V^T [bh][dk][j] bf16 hi/lo directly.
                    // dk is even; dk+1 stays within the same head.
                    int bb0 = r0 >> 8, j0i = r0 & 255;
                    int bb1 = r1 >> 8, j1i = r1 & 255;
                    size_t a0 = ((size_t)((bb0 * H_ + h) * DK_ + dk)) * L_ + j0i;
                    size_t a1 = ((size_t)((bb1 * H_ + h) * DK_ + dk)) * L_ + j1i;
                    bf16 hh, ll;
                    split_bf(v0.x, hh, ll); g_VThi[a0]      = hh; g_VTlo[a0]      = ll;
                    split_bf(v0.y, hh, ll); g_VThi[a0 + L_] = hh; g_VTlo[a0 + L_] = ll;
                    split_bf(v1.x, hh, ll); g_VThi[a1]      = hh; g_VTlo[a1]      = ll;
                    split_bf(v1.y, hh, ll); g_VThi[a1 + L_] = hh; g_VTlo[a1 + L_] = ll;
                } else {
                    float* d0 = Y + ((size_t)((r0 >> 8) * H_ + h) * L_ + (r0 & 255)) * DK_ + dk;
                    float* d1 = Y + ((size_t)((r1 >> 8) * H_ + h) * L_ + (r1 & 255)) * DK_ + dk;
                    *(float2*)d0 = v0;
                    *(float2*)d1 = v1;
                }
            } else {
                *(float2*)(Y + (size_t)r0 * D_ + cng) = v0;
                *(float2*)(Y + (size_t)r1 * D_ + cng) = v1;
            }
        }
    }
}

// QKV: NT=128, fused fp32 split. grid (8, 4, 3) = 96 CTAs (one wave).
// z=2 (V) writes V^T bf16 hi/lo directly (convert_vT fused away).
__global__ __launch_bounds__(256) void qkv_mma_kernel(
    const float* __restrict__ q, const float* __restrict__ k, const float* __restrict__ v,
    const float* __restrict__ bq, const float* __restrict__ bk, const float* __restrict__ bv)
{
    int z = blockIdx.z;
    const float* X    = (z == 0) ? q  : (z == 1 ? k  : v);
    const float* bias = (z == 0) ? bq : (z == 1 ? bk : bv);
    float* out        = (z == 0) ? g_qh : (z == 1 ? g_kh : nullptr);
    gemm_core<128, true, true>(X, nullptr, nullptr,
                               g_Whi + (size_t)z * (512*512), g_Wlo + (size_t)z * (512*512),
                               bias, out, z == 2);
}

// Output projection: NT=64, bf16 ctx input. grid (8, 8) = 64 CTAs.
__global__ __launch_bounds__(256, 2) void out_mma_kernel(
    const float* __restrict__ b0, float* __restrict__ Y)
{
    gemm_core<64, false, false>(nullptr, g_ctx_hi, g_ctx_lo,
                                g_Whi + (size_t)3 * (512*512), g_Wlo + (size_t)3 * (512*512),
                                b0, Y, false);
}

// ---------------------------------------------------------------------------
// Scores: grid (8, 4, 32) = 1024 CTAs, 256 thr, smem ~26KB.
// i-tile 32, j-tile 64; thread = 2i x 4j. Writes E bf16 hi/lo + row partials.
// ---------------------------------------------------------------------------
#define SCQ_ST 34
#define SCK_ST 68

__global__ __launch_bounds__(256) void scores_kernel(
    const int* __restrict__ mask, const float* __restrict__ vp)
{
    __shared__ float Qs[64 * SCQ_ST];
    __shared__ float Ks[64 * SCK_ST];
    __shared__ float vps[64];

    const int tid = threadIdx.x;
    const int bh = blockIdx.z;
    const int b = bh >> 3, h = bh & 7;
    const int i0 = blockIdx.x * 32, j0 = blockIdx.y * 64;
    const int jb = blockIdx.y;

    const float* qh = g_qh + (size_t)(bh * L_ + i0) * DK_;
    const float* kh = g_kh + (size_t)(bh * L_ + j0) * DK_;

    if (tid < 64) vps[tid] = vp[h * DK_ + tid];
    {
        int r = tid >> 3, d0 = (tid & 7) * 8;
        float4 t0 = *(const float4*)&qh[(size_t)r * DK_ + d0];
        float4 t1 = *(const float4*)&qh[(size_t)r * DK_ + d0 + 4];
        Qs[(d0 + 0) * SCQ_ST + r] = t0.x; Qs[(d0 + 1) * SCQ_ST + r] = t0.y;
        Qs[(d0 + 2) * SCQ_ST + r] = t0.z; Qs[(d0 + 3) * SCQ_ST + r] = t0.w;
        Qs[(d0 + 4) * SCQ_ST + r] = t1.x; Qs[(d0 + 5) * SCQ_ST + r] = t1.y;
        Qs[(d0 + 6) * SCQ_ST + r] = t1.z; Qs[(d0 + 7) * SCQ_ST + r] = t1.w;
    }
    {
        int r = tid >> 2, d0 = (tid & 3) * 16;
        #pragma unroll
        for (int u = 0; u < 4; u++) {
            float4 t = *(const float4*)&kh[(size_t)r * DK_ + d0 + u * 4];
            Ks[(d0 + u * 4 + 0) * SCK_ST + r] = t.x;
            Ks[(d0 + u * 4 + 1) * SCK_ST + r] = t.y;
            Ks[(d0 + u * 4 + 2) * SCK_ST + r] = t.z;
            Ks[(d0 + u * 4 + 3) * SCK_ST + r] = t.w;
        }
    }
    __syncthreads();

    const int il2 = tid >> 4;
    const int jg  = tid & 15;

    float acc[2][4] = {};
    #pragma unroll 2
    for (int d = 0; d < 64; d++) {
        float w = vps[d];
        float2 qv = *(const float2*)&Qs[d * SCQ_ST + il2 * 2];
        float4 kv = *(const float4*)&Ks[d * SCK_ST + jg * 4];
        float qa[2] = {qv.x, qv.y};
        float kb[4] = {kv.x, kv.y, kv.z, kv.w};
        #pragma unroll
        for (int a = 0; a < 2; a++)
            #pragma unroll
            for (int c = 0; c < 4; c++)
                acc[a][c] += w * tanh_fast(qa[a] + kb[c]);
    }

    float rpart[2];
    #pragma unroll
    for (int a = 0; a < 2; a++) {
        int row = i0 + il2 * 2 + a;
        const int4 m = *(const int4*)(mask + ((size_t)b * L_ + row) * L_ + j0 + jg * 4);
        float e0 = m.x ? __expf(acc[a][0]) : 0.0f;
        float e1 = m.y ? __expf(acc[a][1]) : 0.0f;
        float e2 = m.z ? __expf(acc[a][2]) : 0.0f;
        float e3 = m.w ? __expf(acc[a][3]) : 0.0f;
        rpart[a] = (e0 + e1) + (e2 + e3);
        bf16 h0, l0, h1, l1, h2, l2, h3, l3;
        split_bf(e0, h0, l0); split_bf(e1, h1, l1);
        split_bf(e2, h2, l2); split_bf(e3, h3, l3);
        size_t off = (size_t)bh * (L_ * L_) + (size_t)row * L_ + j0 + jg * 4;
        bf162* ph = (bf162*)&g_Ehi[off];
        bf162* pl = (bf162*)&g_Elo[off];
        ph[0] = bf162(h0, h1); ph[1] = bf162(h2, h3);
        pl[0] = bf162(l0, l1); pl[1] = bf162(l2, l3);
    }
    #pragma unroll
    for (int a = 0; a < 2; a++) {
        #pragma unroll
        for (int off = 8; off > 0; off >>= 1)
            rpart[a] += __shfl_xor_sync(0xFFFFFFFFu, rpart[a], off);
    }
    if (jg == 0) {
        int row = i0 + il2 * 2;
        float* dst = g_rsum4 + ((size_t)(bh * 4 + jb)) * L_ + row;
        dst[0] = rpart[0];
        dst[1] = rpart[1];
    }
}

// ---------------------------------------------------------------------------
// PV via tensor cores: ctx[i][dk] = (1/rowsum) * sum_j E[i][j] * VT[dk][j]
// K=256 (8 stages). grid (2, 32) = 64 CTAs.
// ---------------------------------------------------------------------------
#define B_HALVES64 (64*SA)
#define PVBUF_H (2*A_HALVES + 2*B_HALVES64)

__global__ __launch_bounds__(256) void pv_mma_kernel()
{
    extern __shared__ __align__(16) bf16 smh[];
    const int tid = threadIdx.x;
    const int lane = tid & 31, wid = tid >> 5;
    const int g = lane >> 2, t4 = lane & 3;
    const int warp_m = (wid & 3) * 32;
    const int warp_n = (wid >> 2) * 32;
    const int m0 = blockIdx.x * 128;
    const int bhz = blockIdx.y;
    const int b = bhz >> 3, h = bhz & 7;

    const bf16* Ahi_g = g_Ehi + (size_t)bhz * (L_ * L_);
    const bf16* Alo_g = g_Elo + (size_t)bhz * (L_ * L_);
    const bf16* Bhi_g = g_VThi + (size_t)bhz * (DK_ * L_);
    const bf16* Blo_g = g_VTlo + (size_t)bhz * (DK_ * L_);

    const int am = tid >> 1, ah = (tid & 1) * 16;
    const int bn = tid >> 2, bo = (tid & 3) * 8;
    const bf16* Asrc_h = Ahi_g + (size_t)(m0 + am) * L_ + ah;
    const bf16* Asrc_l = Alo_g + (size_t)(m0 + am) * L_ + ah;
    const bf16* Bsrc_h = Bhi_g + (size_t)bn * L_ + bo;
    const bf16* Bsrc_l = Blo_g + (size_t)bn * L_ + bo;

    float acc[2][4][4];
    #pragma unroll
    for (int i = 0; i < 2; i++)
        #pragma unroll
        for (int j = 0; j < 4; j++)
            #pragma unroll
            for (int c = 0; c < 4; c++) acc[i][j][c] = 0.0f;

    const int lrow = lane & 15;
    const int lk   = (lane >> 4) * 8;
    const int bln  = lane & 7;
    const int bseg = (lane >> 3) & 1;
    const int bhi16 = (lane >> 4);
    const uint32_t smem_base = smem_u32(smh);
    const uint32_t aoff0 = ((warp_m + lrow)      * SA + lk) * 2;
    const uint32_t aoff1 = ((warp_m + 16 + lrow) * SA + lk) * 2;
    const uint32_t boff0 = ((warp_n + bln)       * SA + bseg * 8) * 2 + bhi16 * (8 * SA * 2);
    const uint32_t boff1 = boff0 + 16 * SA * 2;

    uint4 rAh0, rAh1, rAl0, rAl1, rBh, rBl;
    rAh0 = *(const uint4*)(Asrc_h);  rAh1 = *(const uint4*)(Asrc_h + 8);
    rAl0 = *(const uint4*)(Asrc_l);  rAl1 = *(const uint4*)(Asrc_l + 8);
    rBh  = *(const uint4*)(Bsrc_h);  rBl  = *(const uint4*)(Bsrc_l);

    for (int s = 0; s < 8; s++) {
        const int buf = s & 1;
        bf16* Ah_s = smh + buf * PVBUF_H;
        bf16* Al_s = Ah_s + A_HALVES;
        bf16* Bh_s = Al_s + A_HALVES;
        bf16* Bl_s = Bh_s + B_HALVES64;

        *(uint4*)&Ah_s[am * SA + ah]     = rAh0;
        *(uint4*)&Ah_s[am * SA + ah + 8] = rAh1;
        *(uint4*)&Al_s[am * SA + ah]     = rAl0;
        *(uint4*)&Al_s[am * SA + ah + 8] = rAl1;
        *(uint4*)&Bh_s[bn * SA + bo] = rBh;
        *(uint4*)&Bl_s[bn * SA + bo] = rBl;
        __syncthreads();

        if (s < 7) {
            const int off = (s + 1) * 32;
            rAh0 = *(const uint4*)(Asrc_h + off); rAh1 = *(const uint4*)(Asrc_h + off + 8);
            rAl0 = *(const uint4*)(Asrc_l + off); rAl1 = *(const uint4*)(Asrc_l + off + 8);
            rBh  = *(const uint4*)(Bsrc_h + off); rBl  = *(const uint4*)(Bsrc_l + off);
        }

        const uint32_t base = smem_base + (uint32_t)(buf * PVBUF_H * 2);
        const uint32_t aBh = base;
        const uint32_t aBl = base + A_HALVES * 2;
        const uint32_t bBh = base + 2 * A_HALVES * 2;
        const uint32_t bBl = bBh + B_HALVES64 * 2;

        #pragma unroll
        for (int kk = 0; kk < 2; kk++) {
            const uint32_t ko = kk * 32;
            uint32_t Ah0[4], Ah1[4], Al0[4], Al1[4];
            uint32_t Bh0[4], Bh1[4], Bl0[4], Bl1[4];
            ldm_x4(Ah0, aBh + aoff0 + ko);
            ldm_x4(Ah1, aBh + aoff1 + ko);
            ldm_x4(Al0, aBl + aoff0 + ko);
            ldm_x4(Al1, aBl + aoff1 + ko);
            ldm_x4(Bh0, bBh + boff0 + ko);
            ldm_x4(Bh1, bBh + boff1 + ko);
            ldm_x4(Bl0, bBl + boff0 + ko);
            ldm_x4(Bl1, bBl + boff1 + ko);

            #pragma unroll
            for (int i = 0; i < 2; i++) {
                uint32_t* ahp = i ? Ah1 : Ah0;
                uint32_t* alp = i ? Al1 : Al0;
                #pragma unroll
                for (int j = 0; j < 4; j++) {
                    uint32_t* bhp = (j < 2) ? Bh0 : Bh1;
                    uint32_t* blp = (j < 2) ? Bl0 : Bl1;
                    uint32_t bhf[2] = { bhp[(j & 1) * 2], bhp[(j & 1) * 2 + 1] };
                    uint32_t blf[2] = { blp[(j & 1) * 2], blp[(j & 1) * 2 + 1] };
                    mma_bf16(acc[i][j], ahp, bhf);
                    mma_bf16(acc[i][j], ahp, blf);
                    mma_bf16(acc[i][j], alp, bhf);
                }
            }
        }
    }

    const float* rs = g_rsum4 + (size_t)(bhz * 4) * L_;
    #pragma unroll
    for (int i = 0; i < 2; i++) {
        #pragma unroll
        for (int j = 0; j < 4; j++) {
            int col_loc = warp_n + (j >> 1) * 16 + (j & 1) * 8 + 2 * t4;
            int r0 = m0 + warp_m + i * 16 + g;
            int r1 = r0 + 8;
            float inv0 = 1.0f / ((rs[r0] + rs[L_ + r0]) + (rs[2 * L_ + r0] + rs[3 * L_ + r0]));
            float inv1 = 1.0f / ((rs[r1] + rs[L_ + r1]) + (rs[2 * L_ + r1] + rs[3 * L_ + r1]));
            float v00 = acc[i][j][0] * inv0, v01 = acc[i][j][1] * inv0;
            float v10 = acc[i][j][2] * inv1, v11 = acc[i][j][3] * inv1;
            bf16 ha, la, hb, lb;
            size_t o0 = ((size_t)(b * L_ + r0)) * D_ + h * DK_ + col_loc;
            size_t o1 = ((size_t)(b * L_ + r1)) * D_ + h * DK_ + col_loc;
            split_bf(v00, ha, la); split_bf(v01, hb, lb);
            *(bf162*)&g_ctx_hi[o0] = bf162(ha, hb);
            *(bf162*)&g_ctx_lo[o0] = bf162(la, lb);
            split_bf(v10, ha, la); split_bf(v11, hb, lb);
            *(bf162*)&g_ctx_hi[o1] = bf162(ha, hb);
            *(bf162*)&g_ctx_lo[o1] = bf162(la, lb);
        }
    }
}

// ===========================================================================
extern "C" void kernel_launch(void* const* d_in, const int* in_sizes, int n_in,
                              void* d_out, int out_size)
{
    const float* q    = (const float*)d_in[0];
    const float* k    = (const float*)d_in[1];
    const float* v    = (const float*)d_in[2];
    const int*   mask = (const int*)  d_in[3];
    const float* Wq   = (const float*)d_in[4];
    const float* bq   = (const float*)d_in[5];
    const float* Wk   = (const float*)d_in[6];
    const float* bk   = (const float*)d_in[7];
    const float* Wv   = (const float*)d_in[8];
    const float* bv   = (const float*)d_in[9];
    const float* vp   = (const float*)d_in[10];
    const float* W0   = (const float*)d_in[11];
    const float* b0   = (const float*)d_in[12];
    float* out = (float*)d_out;

    static bool attr_set = false;
    if (!attr_set) {
        cudaFuncSetAttribute(qkv_mma_kernel,
                             cudaFuncAttributeMaxDynamicSharedMemorySize, gemm_smem_b(128));
        cudaFuncSetAttribute(out_mma_kernel,
                             cudaFuncAttributeMaxDynamicSharedMemorySize, gemm_smem_b(64));
        cudaFuncSetAttribute(pv_mma_kernel,
                             cudaFuncAttributeMaxDynamicSharedMemorySize, gemm_smem_b(64));
        attr_set = true;
    }

    convert_w_kernel<<<dim3(16, 16, 4), dim3(32, 8)>>>(Wq, Wk, Wv, W0);
    qkv_mma_kernel<<<dim3(8, 4, 3), 256, gemm_smem_b(128)>>>(q, k, v, bq, bk, bv);
    scores_kernel<<<dim3(8, 4, 32), 256>>>(mask, vp);
    pv_mma_kernel<<<dim3(2, 32), 256, gemm_smem_b(64)>>>();
    out_mma_kernel<<<dim3(8, 8), 256, gemm_smem_b(64)>>>(b0, out);
}

// round 16
// speedup vs baseline: 1.0652x; 1.0652x over previous
#include <cuda_runtime.h>
#include <cuda_bf16.h>
#include <cstdint>
#include <math.h>

#define B_ 4
#define L_ 256
#define D_ 512
#define H_ 8
#define DK_ 64

typedef __nv_bfloat16 bf16;
typedef __nv_bfloat162 bf162;

// ---------------------------------------------------------------------------
// Scratch (allocation-free rule: __device__ globals)
// ---------------------------------------------------------------------------
__device__ float g_qh[B_*H_*L_*DK_];
__device__ float g_kh[B_*H_*L_*DK_];
__device__ float g_vh[B_*H_*L_*DK_];
__device__ float g_rsum4[B_*H_*4*L_];               // per-jblock row partial sums

__device__ __align__(16) bf16 g_Ehi[B_*H_*L_*L_];   // exp(scores) hi
__device__ __align__(16) bf16 g_Elo[B_*H_*L_*L_];   // exp(scores) lo
__device__ __align__(16) bf16 g_VThi[B_*H_*DK_*L_]; // V^T [bh][dk][j]
__device__ __align__(16) bf16 g_VTlo[B_*H_*DK_*L_];

__device__ __align__(16) bf16 g_Whi[4*512*512];    // Wq,Wk,Wv,W0 TRANSPOSED [n][k]
__device__ __align__(16) bf16 g_Wlo[4*512*512];
__device__ __align__(16) bf16 g_ctx_hi[1024*512];  // attention context [m][k]
__device__ __align__(16) bf16 g_ctx_lo[1024*512];

// ---------------------------------------------------------------------------
__device__ __forceinline__ uint32_t smem_u32(const void* p) {
    uint32_t a;
    asm("{ .reg .u64 t; cvta.to.shared.u64 t, %1; cvt.u32.u64 %0, t; }" : "=r"(a) : "l"(p));
    return a;
}
__device__ __forceinline__ float tanh_fast(float x) {
    float y;
    asm("tanh.approx.f32 %0, %1;" : "=f"(y) : "f"(x));
    return y;
}
__device__ __forceinline__ void ldm_x4(uint32_t* r, uint32_t addr) {
    asm volatile("ldmatrix.sync.aligned.m8n8.x4.shared.b16 {%0,%1,%2,%3}, [%4];"
        : "=r"(r[0]), "=r"(r[1]), "=r"(r[2]), "=r"(r[3]) : "r"(addr));
}
__device__ __forceinline__ void mma_bf16(float* c, const uint32_t* a, const uint32_t* b) {
    asm volatile(
        "mma.sync.aligned.m16n8k16.row.col.f32.bf16.bf16.f32 "
        "{%0,%1,%2,%3}, {%4,%5,%6,%7}, {%8,%9}, {%0,%1,%2,%3};"
        : "+f"(c[0]), "+f"(c[1]), "+f"(c[2]), "+f"(c[3])
        : "r"(a[0]), "r"(a[1]), "r"(a[2]), "r"(a[3]), "r"(b[0]), "r"(b[1]));
}
__device__ __forceinline__ void split_bf(float x, bf16& hi, bf16& lo) {
    hi = __float2bfloat16_rn(x);
    lo = __float2bfloat16_rn(x - __bfloat162float(hi));
}
__device__ __forceinline__ void split2u(float a, float b, uint32_t& h, uint32_t& l) {
    bf16 ha, la, hb, lb;
    split_bf(a, ha, la);
    split_bf(b, hb, lb);
    bf162 hh(ha, hb), ll(la, lb);
    h = *(uint32_t*)&hh;
    l = *(uint32_t*)&ll;
}

// ---------------------------------------------------------------------------
// W [k][n] -> [n][k] transpose + hi/lo split.  block (32,8), grid (16,16,4)
// ---------------------------------------------------------------------------
__global__ __launch_bounds__(256) void convert_w_kernel(
    const float* __restrict__ Wq, const float* __restrict__ Wk,
    const float* __restrict__ Wv, const float* __restrict__ W0)
{
    __shared__ float tile[32][33];
    int z = blockIdx.z;
    const float* W = (z == 0) ? Wq : (z == 1 ? Wk : (z == 2 ? Wv : W0));
    int k0 = blockIdx.x * 32, n0 = blockIdx.y * 32;
    int tx = threadIdx.x, ty = threadIdx.y;
    #pragma unroll
    for (int it = 0; it < 4; it++)
        tile[ty + it * 8][tx] = W[(size_t)(k0 + ty + it * 8) * D_ + n0 + tx];
    __syncthreads();
    size_t zb = (size_t)z * (512*512);
    #pragma unroll
    for (int it = 0; it < 4; it++) {
        int nr = ty + it * 8;
        bf16 hi, lo;
        split_bf(tile[tx][nr], hi, lo);
        g_Whi[zb + (size_t)(n0 + nr) * D_ + k0 + tx] = hi;
        g_Wlo[zb + (size_t)(n0 + nr) * D_ + k0 + tx] = lo;
    }
}

// V [bh][j][dk] fp32 -> VT [bh][dk][j] bf16 hi/lo. grid (8, 2, 32), block (32,8)
__global__ __launch_bounds__(256) void convert_vT_kernel()
{
    __shared__ float tile[32][33];
    int bh = blockIdx.z;
    int j0 = blockIdx.x * 32, d0 = blockIdx.y * 32;
    int tx = threadIdx.x, ty = threadIdx.y;
    const float* vsrc = g_vh + (size_t)bh * (L_ * DK_);
    #pragma unroll
    for (int it = 0; it < 4; it++)
        tile[ty + it * 8][tx] = vsrc[(size_t)(j0 + ty + it * 8) * DK_ + d0 + tx];
    __syncthreads();
    size_t base = (size_t)bh * (DK_ * L_);
    #pragma unroll
    for (int it = 0; it < 4; it++) {
        int nr = ty + it * 8;
        bf16 hi, lo;
        split_bf(tile[tx][nr], hi, lo);
        g_VThi[base + (size_t)(d0 + nr) * L_ + j0 + tx] = hi;
        g_VTlo[base + (size_t)(d0 + nr) * L_ + j0 + tx] = lo;
    }
}

// ---------------------------------------------------------------------------
// 3xBF16 tensor-core GEMM, templated tile width (qkv / out projection).
// ---------------------------------------------------------------------------
#define SA 40
#define A_HALVES (128*SA)

constexpr int gemm_smem_b(int nt) {
    return 2 * (2 * A_HALVES + 2 * nt * SA) * 2;
}

template<int NT, bool HEADSPLIT, bool AFP32>
__device__ __forceinline__ void gemm_core(
    const float* __restrict__ Af_g,
    const bf16* __restrict__ Ahi_g, const bf16* __restrict__ Alo_g,
    const bf16* __restrict__ Bhi_g, const bf16* __restrict__ Blo_g,
    const float* __restrict__ bias, float* __restrict__ Y)
{
    constexpr int NTILES = NT / 16;
    constexpr int NB = NTILES / 2;
    constexpr int B_HALVES_T = NT * SA;
    constexpr int BUF_H = 2 * A_HALVES + 2 * B_HALVES_T;
    constexpr int TPRB = 256 / NT;
    constexpr int BPT = NT / 64;

    extern __shared__ __align__(16) bf16 smh[];
    const int tid = threadIdx.x;
    const int lane = tid & 31, wid = tid >> 5;
    const int g = lane >> 2, t4 = lane & 3;
    const int warp_m = (wid & 3) * 32;
    const int warp_n = (wid >> 2) * (NT / 2);
    const int m0 = blockIdx.x * 128, n0 = blockIdx.y * NT;

    const int am = tid >> 1, ahh = (tid & 1) * 16;
    const int bn = tid / TPRB, bo = (tid % TPRB) * (32 / TPRB);

    const float* Af = Af_g ? Af_g + (size_t)(m0 + am) * D_ + ahh : (const float*)0;
    const bf16* Ash = Ahi_g ? Ahi_g + (size_t)(m0 + am) * D_ + ahh : (const bf16*)0;
    const bf16* Asl = Alo_g ? Alo_g + (size_t)(m0 + am) * D_ + ahh : (const bf16*)0;
    const bf16* Bsh = Bhi_g + (size_t)(n0 + bn) * D_ + bo;
    const bf16* Bsl = Blo_g + (size_t)(n0 + bn) * D_ + bo;

    float acc[2][NTILES][4];
    #pragma unroll
    for (int i = 0; i < 2; i++)
        #pragma unroll
        for (int j = 0; j < NTILES; j++)
            #pragma unroll
            for (int c = 0; c < 4; c++) acc[i][j][c] = 0.0f;

    const int lrow = lane & 15;
    const int lk   = (lane >> 4) * 8;
    const int bln  = lane & 7;
    const int bseg = (lane >> 3) & 1;
    const int bhi16 = (lane >> 4);
    const uint32_t smem_base = smem_u32(smh);
    const uint32_t aoff0 = ((warp_m + lrow)      * SA + lk) * 2;
    const uint32_t aoff1 = ((warp_m + 16 + lrow) * SA + lk) * 2;
    uint32_t boffs[NB];
    #pragma unroll
    for (int t = 0; t < NB; t++)
        boffs[t] = ((warp_n + t * 16 + bln) * SA + bseg * 8) * 2 + bhi16 * (8 * SA * 2);

    float4 rAf[4];
    uint4 rA_h[2], rA_l[2];
    uint4 rB_h[BPT], rB_l[BPT];

    if (AFP32) {
        #pragma unroll
        for (int u = 0; u < 4; u++) rAf[u] = *(const float4*)(Af + u * 4);
    } else {
        rA_h[0] = *(const uint4*)(Ash);     rA_h[1] = *(const uint4*)(Ash + 8);
        rA_l[0] = *(const uint4*)(Asl);     rA_l[1] = *(const uint4*)(Asl + 8);
    }
    #pragma unroll
    for (int p = 0; p < BPT; p++) {
        rB_h[p] = *(const uint4*)(Bsh + p * 8);
        rB_l[p] = *(const uint4*)(Bsl + p * 8);
    }

    for (int s = 0; s < 16; s++) {
        const int buf = s & 1;
        bf16* Ah_s = smh + buf * BUF_H;
        bf16* Al_s = Ah_s + A_HALVES;
        bf16* Bh_s = Al_s + A_HALVES;
        bf16* Bl_s = Bh_s + B_HALVES_T;

        if (AFP32) {
            uint32_t h[8], l[8];
            #pragma unroll
            for (int u = 0; u < 4; u++) {
                split2u(rAf[u].x, rAf[u].y, h[2 * u],     l[2 * u]);
                split2u(rAf[u].z, rAf[u].w, h[2 * u + 1], l[2 * u + 1]);
            }
            *(uint4*)&Ah_s[am * SA + ahh]     = make_uint4(h[0], h[1], h[2], h[3]);
            *(uint4*)&Ah_s[am * SA + ahh + 8] = make_uint4(h[4], h[5], h[6], h[7]);
            *(uint4*)&Al_s[am * SA + ahh]     = make_uint4(l[0], l[1], l[2], l[3]);
            *(uint4*)&Al_s[am * SA + ahh + 8] = make_uint4(l[4], l[5], l[6], l[7]);
        } else {
            *(uint4*)&Ah_s[am * SA + ahh]     = rA_h[0];
            *(uint4*)&Ah_s[am * SA + ahh + 8] = rA_h[1];
            *(uint4*)&Al_s[am * SA + ahh]     = rA_l[0];
            *(uint4*)&Al_s[am * SA + ahh + 8] = rA_l[1];
        }
        #pragma unroll
        for (int p = 0; p < BPT; p++) {
            *(uint4*)&Bh_s[bn * SA + bo + p * 8] = rB_h[p];
            *(uint4*)&Bl_s[bn * SA + bo + p * 8] = rB_l[p];
        }
        __syncthreads();

        if (s < 15) {
            const int off = (s + 1) * 32;
            if (AFP32) {
                #pragma unroll
                for (int u = 0; u < 4; u++) rAf[u] = *(const float4*)(Af + off + u * 4);
            } else {
                rA_h[0] = *(const uint4*)(Ash + off); rA_h[1] = *(const uint4*)(Ash + off + 8);
                rA_l[0] = *(const uint4*)(Asl + off); rA_l[1] = *(const uint4*)(Asl + off + 8);
            }
            #pragma unroll
            for (int p = 0; p < BPT; p++) {
                rB_h[p] = *(const uint4*)(Bsh + off + p * 8);
                rB_l[p] = *(const uint4*)(Bsl + off + p * 8);
            }
        }

        const uint32_t base = smem_base + (uint32_t)(buf * BUF_H * 2);
        const uint32_t aBh = base;
        const uint32_t aBl = base + A_HALVES * 2;
        const uint32_t bBh = base + 2 * A_HALVES * 2;
        const uint32_t bBl = bBh + B_HALVES_T * 2;

        #pragma unroll
        for (int kk = 0; kk < 2; kk++) {
            const uint32_t ko = kk * 32;
            uint32_t Ah0[4], Ah1[4], Al0[4], Al1[4];
            uint32_t Bh[NB][4], Bl[NB][4];
            ldm_x4(Ah0, aBh + aoff0 + ko);
            ldm_x4(Ah1, aBh + aoff1 + ko);
            ldm_x4(Al0, aBl + aoff0 + ko);
            ldm_x4(Al1, aBl + aoff1 + ko);
            #pragma unroll
            for (int t = 0; t < NB; t++) {
                ldm_x4(Bh[t], bBh + boffs[t] + ko);
                ldm_x4(Bl[t], bBl + boffs[t] + ko);
            }

            #pragma unroll
            for (int i = 0; i < 2; i++) {
                uint32_t* ahp = i ? Ah1 : Ah0;
                uint32_t* alp = i ? Al1 : Al0;
                #pragma unroll
                for (int j = 0; j < NTILES; j++) {
                    uint32_t* bhp = Bh[j >> 1];
                    uint32_t* blp = Bl[j >> 1];
                    uint32_t bhf[2] = { bhp[(j & 1) * 2], bhp[(j & 1) * 2 + 1] };
                    uint32_t blf[2] = { blp[(j & 1) * 2], blp[(j & 1) * 2 + 1] };
                    mma_bf16(acc[i][j], ahp, bhf);
                    mma_bf16(acc[i][j], ahp, blf);
                    mma_bf16(acc[i][j], alp, bhf);
                }
            }
        }
    }

    #pragma unroll
    for (int i = 0; i < 2; i++) {
        #pragma unroll
        for (int j = 0; j < NTILES; j++) {
            int col_loc = warp_n + (j >> 1) * 16 + (j & 1) * 8 + 2 * t4;
            int cng = n0 + col_loc;
            float b0 = bias[cng], b1 = bias[cng + 1];
            int r0 = m0 + warp_m + i * 16 + g;
            int r1 = r0 + 8;
            float2 v0 = make_float2(acc[i][j][0] + b0, acc[i][j][1] + b1);
            float2 v1 = make_float2(acc[i][j][2] + b0, acc[i][j][3] + b1);
            if (HEADSPLIT) {
                int h = cng >> 6, dk = cng & 63;
                float* d0 = Y + ((size_t)((r0 >> 8) * H_ + h) * L_ + (r0 & 255)) * DK_ + dk;
                float* d1 = Y + ((size_t)((r1 >> 8) * H_ + h) * L_ + (r1 & 255)) * DK_ + dk;
                *(float2*)d0 = v0;
                *(float2*)d1 = v1;
            } else {
                *(float2*)(Y + (size_t)r0 * D_ + cng) = v0;
                *(float2*)(Y + (size_t)r1 * D_ + cng) = v1;
            }
        }
    }
}

// QKV: NT=128, fused fp32 split. grid (8, 4, 3) = 96 CTAs (one wave).
__global__ __launch_bounds__(256) void qkv_mma_kernel(
    const float* __restrict__ q, const float* __restrict__ k, const float* __restrict__ v,
    const float* __restrict__ bq, const float* __restrict__ bk, const float* __restrict__ bv)
{
    int z = blockIdx.z;
    const float* X    = (z == 0) ? q  : (z == 1 ? k  : v);
    const float* bias = (z == 0) ? bq : (z == 1 ? bk : bv);
    float* out        = (z == 0) ? g_qh : (z == 1 ? g_kh : g_vh);
    gemm_core<128, true, true>(X, nullptr, nullptr,
                               g_Whi + (size_t)z * (512*512), g_Wlo + (size_t)z * (512*512),
                               bias, out);
}

// Output projection: NT=64, bf16 ctx input. grid (8, 8) = 64 CTAs.
__global__ __launch_bounds__(256, 2) void out_mma_kernel(
    const float* __restrict__ b0, float* __restrict__ Y)
{
    gemm_core<64, false, false>(nullptr, g_ctx_hi, g_ctx_lo,
                                g_Whi + (size_t)3 * (512*512), g_Wlo + (size_t)3 * (512*512),
                                b0, Y);
}

// ---------------------------------------------------------------------------
// Scores: grid (8, 4, 32) = 1024 CTAs, 256 thr, smem ~26KB.
// ---------------------------------------------------------------------------
#define SCQ_ST 34
#define SCK_ST 68

__global__ __launch_bounds__(256) void scores_kernel(
    const int* __restrict__ mask, const float* __restrict__ vp)
{
    __shared__ float Qs[64 * SCQ_ST];
    __shared__ float Ks[64 * SCK_ST];
    __shared__ float vps[64];

    const int tid = threadIdx.x;
    const int bh = blockIdx.z;
    const int b = bh >> 3, h = bh & 7;
    const int i0 = blockIdx.x * 32, j0 = blockIdx.y * 64;
    const int jb = blockIdx.y;

    const float* qh = g_qh + (size_t)(bh * L_ + i0) * DK_;
    const float* kh = g_kh + (size_t)(bh * L_ + j0) * DK_;

    if (tid < 64) vps[tid] = vp[h * DK_ + tid];
    {
        int r = tid >> 3, d0 = (tid & 7) * 8;
        float4 t0 = *(const float4*)&qh[(size_t)r * DK_ + d0];
        float4 t1 = *(const float4*)&qh[(size_t)r * DK_ + d0 + 4];
        Qs[(d0 + 0) * SCQ_ST + r] = t0.x; Qs[(d0 + 1) * SCQ_ST + r] = t0.y;
        Qs[(d0 + 2) * SCQ_ST + r] = t0.z; Qs[(d0 + 3) * SCQ_ST + r] = t0.w;
        Qs[(d0 + 4) * SCQ_ST + r] = t1.x; Qs[(d0 + 5) * SCQ_ST + r] = t1.y;
        Qs[(d0 + 6) * SCQ_ST + r] = t1.z; Qs[(d0 + 7) * SCQ_ST + r] = t1.w;
    }
    {
        int r = tid >> 2, d0 = (tid & 3) * 16;
        #pragma unroll
        for (int u = 0; u < 4; u++) {
            float4 t = *(const float4*)&kh[(size_t)r * DK_ + d0 + u * 4];
            Ks[(d0 + u * 4 + 0) * SCK_ST + r] = t.x;
            Ks[(d0 + u * 4 + 1) * SCK_ST + r] = t.y;
            Ks[(d0 + u * 4 + 2) * SCK_ST + r] = t.z;
            Ks[(d0 + u * 4 + 3) * SCK_ST + r] = t.w;
        }
    }
    __syncthreads();

    const int il2 = tid >> 4;
    const int jg  = tid & 15;

    float acc[2][4] = {};
    #pragma unroll 2
    for (int d = 0; d < 64; d++) {
        float w = vps[d];
        float2 qv = *(const float2*)&Qs[d * SCQ_ST + il2 * 2];
        float4 kv = *(const float4*)&Ks[d * SCK_ST + jg * 4];
        float qa[2] = {qv.x, qv.y};
        float kb[4] = {kv.x, kv.y, kv.z, kv.w};
        #pragma unroll
        for (int a = 0; a < 2; a++)
            #pragma unroll
            for (int c = 0; c < 4; c++)
                acc[a][c] += w * tanh_fast(qa[a] + kb[c]);
    }

    float rpart[2];
    #pragma unroll
    for (int a = 0; a < 2; a++) {
        int row = i0 + il2 * 2 + a;
        const int4 m = *(const int4*)(mask + ((size_t)b * L_ + row) * L_ + j0 + jg * 4);
        float e0 = m.x ? __expf(acc[a][0]) : 0.0f;
        float e1 = m.y ? __expf(acc[a][1]) : 0.0f;
        float e2 = m.z ? __expf(acc[a][2]) : 0.0f;
        float e3 = m.w ? __expf(acc[a][3]) : 0.0f;
        rpart[a] = (e0 + e1) + (e2 + e3);
        bf16 h0, l0, h1, l1, h2, l2, h3, l3;
        split_bf(e0, h0, l0); split_bf(e1, h1, l1);
        split_bf(e2, h2, l2); split_bf(e3, h3, l3);
        size_t off = (size_t)bh * (L_ * L_) + (size_t)row * L_ + j0 + jg * 4;
        bf162* ph = (bf162*)&g_Ehi[off];
        bf162* pl = (bf162*)&g_Elo[off];
        ph[0] = bf162(h0, h1); ph[1] = bf162(h2, h3);
        pl[0] = bf162(l0, l1); pl[1] = bf162(l2, l3);
    }
    #pragma unroll
    for (int a = 0; a < 2; a++) {
        #pragma unroll
        for (int off = 8; off > 0; off >>= 1)
            rpart[a] += __shfl_xor_sync(0xFFFFFFFFu, rpart[a], off);
    }
    if (jg == 0) {
        int row = i0 + il2 * 2;
        float* dst = g_rsum4 + ((size_t)(bh * 4 + jb)) * L_ + row;
        dst[0] = rpart[0];
        dst[1] = rpart[1];
    }
}

// ---------------------------------------------------------------------------
// PV via tensor cores, M-tile 64: grid (4, 32) = 128 CTAs, 256 thr.
// ctx[i][dk] = (1/rowsum) * sum_j E[i][j] * VT[dk][j].  K=256, 8 stages.
// Warps: 2(M) x 4(N); warp tile 32x16. smem ~40KB -> 2 CTAs/SM.
// ---------------------------------------------------------------------------
#define PVA_HALVES (64*SA)
#define PVB_HALVES (64*SA)
#define PVBUF_H (2*PVA_HALVES + 2*PVB_HALVES)
#define PV_SMEM_BYTES (2*PVBUF_H*2)

__global__ __launch_bounds__(256, 2) void pv_mma_kernel()
{
    extern __shared__ __align__(16) bf16 smh[];
    const int tid = threadIdx.x;
    const int lane = tid & 31, wid = tid >> 5;
    const int g = lane >> 2, t4 = lane & 3;
    const int warp_m = (wid & 1) * 32;
    const int warp_n = (wid >> 1) * 16;
    const int m0 = blockIdx.x * 64;
    const int bhz = blockIdx.y;
    const int b = bhz >> 3, h = bhz & 7;

    const bf16* Ahi_g = g_Ehi + (size_t)bhz * (L_ * L_);
    const bf16* Alo_g = g_Elo + (size_t)bhz * (L_ * L_);
    const bf16* Bhi_g = g_VThi + (size_t)bhz * (DK_ * L_);
    const bf16* Blo_g = g_VTlo + (size_t)bhz * (DK_ * L_);

    const int am = tid >> 2, ao = (tid & 3) * 8;
    const bf16* Asrc_h = Ahi_g + (size_t)(m0 + am) * L_ + ao;
    const bf16* Asrc_l = Alo_g + (size_t)(m0 + am) * L_ + ao;
    const bf16* Bsrc_h = Bhi_g + (size_t)am * L_ + ao;
    const bf16* Bsrc_l = Blo_g + (size_t)am * L_ + ao;

    float acc[2][2][4];
    #pragma unroll
    for (int i = 0; i < 2; i++)
        #pragma unroll
        for (int j = 0; j < 2; j++)
            #pragma unroll
            for (int c = 0; c < 4; c++) acc[i][j][c] = 0.0f;

    const int lrow = lane & 15;
    const int lk   = (lane >> 4) * 8;
    const int bln  = lane & 7;
    const int bseg = (lane >> 3) & 1;
    const int bhi16 = (lane >> 4);
    const uint32_t smem_base = smem_u32(smh);
    const uint32_t aoff0 = ((warp_m + lrow)      * SA + lk) * 2;
    const uint32_t aoff1 = ((warp_m + 16 + lrow) * SA + lk) * 2;
    const uint32_t boff0 = ((warp_n + bln) * SA + bseg * 8) * 2 + bhi16 * (8 * SA * 2);

    uint4 rAh, rAl, rBh, rBl;
    rAh = *(const uint4*)(Asrc_h);
    rAl = *(const uint4*)(Asrc_l);
    rBh = *(const uint4*)(Bsrc_h);
    rBl = *(const uint4*)(Bsrc_l);

    for (int s = 0; s < 8; s++) {
        const int buf = s & 1;
        bf16* Ah_s = smh + buf * PVBUF_H;
        bf16* Al_s = Ah_s + PVA_HALVES;
        bf16* Bh_s = Al_s + PVA_HALVES;
        bf16* Bl_s = Bh_s + PVB_HALVES;

        *(uint4*)&Ah_s[am * SA + ao] = rAh;
        *(uint4*)&Al_s[am * SA + ao] = rAl;
        *(uint4*)&Bh_s[am * SA + ao] = rBh;
        *(uint4*)&Bl_s[am * SA + ao] = rBl;
        __syncthreads();

        if (s < 7) {
            const int off = (s + 1) * 32;
            rAh = *(const uint4*)(Asrc_h + off);
            rAl = *(const uint4*)(Asrc_l + off);
            rBh = *(const uint4*)(Bsrc_h + off);
            rBl = *(const uint4*)(Bsrc_l + off);
        }

        const uint32_t base = smem_base + (uint32_t)(buf * PVBUF_H * 2);
        const uint32_t aBh = base;
        const uint32_t aBl = base + PVA_HALVES * 2;
        const uint32_t bBh = base + 2 * PVA_HALVES * 2;
        const uint32_t bBl = bBh + PVB_HALVES * 2;

        #pragma unroll
        for (int kk = 0; kk < 2; kk++) {
            const uint32_t ko = kk * 32;
            uint32_t Ah0[4], Ah1[4], Al0[4], Al1[4];
            uint32_t Bh0[4], Bl0[4];
            ldm_x4(Ah0, aBh + aoff0 + ko);
            ldm_x4(Ah1, aBh + aoff1 + ko);
            ldm_x4(Al0, aBl + aoff0 + ko);
            ldm_x4(Al1, aBl + aoff1 + ko);
            ldm_x4(Bh0, bBh + boff0 + ko);
            ldm_x4(Bl0, bBl + boff0 + ko);

            #pragma unroll
            for (int i = 0; i < 2; i++) {
                uint32_t* ahp = i ? Ah1 : Ah0;
                uint32_t* alp = i ? Al1 : Al0;
                #pragma unroll
                for (int j = 0; j < 2; j++) {
                    uint32_t bhf[2] = { Bh0[j * 2], Bh0[j * 2 + 1] };
                    uint32_t blf[2] = { Bl0[j * 2], Bl0[j * 2 + 1] };
                    mma_bf16(acc[i][j], ahp, bhf);
                    mma_bf16(acc[i][j], ahp, blf);
                    mma_bf16(acc[i][j], alp, bhf);
                }
            }
        }
    }

    const float* rs = g_rsum4 + (size_t)(bhz * 4) * L_;
    #pragma unroll
    for (int i = 0; i < 2; i++) {
        #pragma unroll
        for (int j = 0; j < 2; j++) {
            int col_loc = warp_n + j * 8 + 2 * t4;
            int r0 = m0 + warp_m + i * 16 + g;
            int r1 = r0 + 8;
            float inv0 = 1.0f / ((rs[r0] + rs[L_ + r0]) + (rs[2 * L_ + r0] + rs[3 * L_ + r0]));
            float inv1 = 1.0f / ((rs[r1] + rs[L_ + r1]) + (rs[2 * L_ + r1] + rs[3 * L_ + r1]));
            float v00 = acc[i][j][0] * inv0, v01 = acc[i][j][1] * inv0;
            float v10 = acc[i][j][2] * inv1, v11 = acc[i][j][3] * inv1;
            bf16 ha, la, hb, lb;
            size_t o0 = ((size_t)(b * L_ + r0)) * D_ + h * DK_ + col_loc;
            size_t o1 = ((size_t)(b * L_ + r1)) * D_ + h * DK_ + col_loc;
            split_bf(v00, ha, la); split_bf(v01, hb, lb);
            *(bf162*)&g_ctx_hi[o0] = bf162(ha, hb);
            *(bf162*)&g_ctx_lo[o0] = bf162(la, lb);
            split_bf(v10, ha, la); split_bf(v11, hb, lb);
            *(bf162*)&g_ctx_hi[o1] = bf162(ha, hb);
            *(bf162*)&g_ctx_lo[o1] = bf162(la, lb);
        }
    }
}

// ===========================================================================
extern "C" void kernel_launch(void* const* d_in, const int* in_sizes, int n_in,
                              void* d_out, int out_size)
{
    const float* q    = (const float*)d_in[0];
    const float* k    = (const float*)d_in[1];
    const float* v    = (const float*)d_in[2];
    const int*   mask = (const int*)  d_in[3];
    const float* Wq   = (const float*)d_in[4];
    const float* bq   = (const float*)d_in[5];
    const float* Wk   = (const float*)d_in[6];
    const float* bk   = (const float*)d_in[7];
    const float* Wv   = (const float*)d_in[8];
    const float* bv   = (const float*)d_in[9];
    const float* vp   = (const float*)d_in[10];
    const float* W0   = (const float*)d_in[11];
    const float* b0   = (const float*)d_in[12];
    float* out = (float*)d_out;

    static bool attr_set = false;
    if (!attr_set) {
        cudaFuncSetAttribute(qkv_mma_kernel,
                             cudaFuncAttributeMaxDynamicSharedMemorySize, gemm_smem_b(128));
        cudaFuncSetAttribute(out_mma_kernel,
                             cudaFuncAttributeMaxDynamicSharedMemorySize, gemm_smem_b(64));
        cudaFuncSetAttribute(pv_mma_kernel,
                             cudaFuncAttributeMaxDynamicSharedMemorySize, PV_SMEM_BYTES);
        attr_set = true;
    }

    convert_w_kernel<<<dim3(16, 16, 4), dim3(32, 8)>>>(Wq, Wk, Wv, W0);
    qkv_mma_kernel<<<dim3(8, 4, 3), 256, gemm_smem_b(128)>>>(q, k, v, bq, bk, bv);
    convert_vT_kernel<<<dim3(8, 2, 32), dim3(32, 8)>>>();
    scores_kernel<<<dim3(8, 4, 32), 256>>>(mask, vp);
    pv_mma_kernel<<<dim3(4, 32), 256, PV_SMEM_BYTES>>>();
    out_mma_kernel<<<dim3(8, 8), 256, gemm_smem_b(64)>>>(b0, out);
}

// round 17
// speedup vs baseline: 1.1344x; 1.0651x over previous
#include <cuda_runtime.h>
#include <cuda_bf16.h>
#include <cstdint>
#include <math.h>

#define B_ 4
#define L_ 256
#define D_ 512
#define H_ 8
#define DK_ 64

typedef __nv_bfloat16 bf16;
typedef __nv_bfloat162 bf162;

// ---------------------------------------------------------------------------
// Scratch (allocation-free rule: __device__ globals)
// ---------------------------------------------------------------------------
__device__ float g_qh[B_*H_*L_*DK_];
__device__ float g_kh[B_*H_*L_*DK_];
__device__ float g_rsum4[B_*H_*4*L_];               // per-jblock row partial sums

__device__ __align__(16) bf16 g_Ehi[B_*H_*L_*L_];   // exp(scores) hi
__device__ __align__(16) bf16 g_Elo[B_*H_*L_*L_];   // exp(scores) lo
__device__ __align__(16) bf16 g_Vhi[B_*H_*L_*DK_];  // V [bh][j][dk] bf16 hi
__device__ __align__(16) bf16 g_Vlo[B_*H_*L_*DK_];  // V [bh][j][dk] bf16 lo

__device__ __align__(16) bf16 g_Whi[4*512*512];    // Wq,Wk,Wv,W0 TRANSPOSED [n][k]
__device__ __align__(16) bf16 g_Wlo[4*512*512];
__device__ __align__(16) bf16 g_ctx_hi[1024*512];  // attention context [m][k]
__device__ __align__(16) bf16 g_ctx_lo[1024*512];

// ---------------------------------------------------------------------------
__device__ __forceinline__ uint32_t smem_u32(const void* p) {
    uint32_t a;
    asm("{ .reg .u64 t; cvta.to.shared.u64 t, %1; cvt.u32.u64 %0, t; }" : "=r"(a) : "l"(p));
    return a;
}
__device__ __forceinline__ float tanh_fast(float x) {
    float y;
    asm("tanh.approx.f32 %0, %1;" : "=f"(y) : "f"(x));
    return y;
}
__device__ __forceinline__ void ldm_x4(uint32_t* r, uint32_t addr) {
    asm volatile("ldmatrix.sync.aligned.m8n8.x4.shared.b16 {%0,%1,%2,%3}, [%4];"
        : "=r"(r[0]), "=r"(r[1]), "=r"(r[2]), "=r"(r[3]) : "r"(addr));
}
__device__ __forceinline__ void ldm_x4_t(uint32_t* r, uint32_t addr) {
    asm volatile("ldmatrix.sync.aligned.m8n8.x4.trans.shared.b16 {%0,%1,%2,%3}, [%4];"
        : "=r"(r[0]), "=r"(r[1]), "=r"(r[2]), "=r"(r[3]) : "r"(addr));
}
__device__ __forceinline__ void mma_bf16(float* c, const uint32_t* a, const uint32_t* b) {
    asm volatile(
        "mma.sync.aligned.m16n8k16.row.col.f32.bf16.bf16.f32 "
        "{%0,%1,%2,%3}, {%4,%5,%6,%7}, {%8,%9}, {%0,%1,%2,%3};"
        : "+f"(c[0]), "+f"(c[1]), "+f"(c[2]), "+f"(c[3])
        : "r"(a[0]), "r"(a[1]), "r"(a[2]), "r"(a[3]), "r"(b[0]), "r"(b[1]));
}
__device__ __forceinline__ void split_bf(float x, bf16& hi, bf16& lo) {
    hi = __float2bfloat16_rn(x);
    lo = __float2bfloat16_rn(x - __bfloat162float(hi));
}
__device__ __forceinline__ void pack8(const float4& a, const float4& b, uint4& h, uint4& l) {
    bf16 h0,l0,h1,l1,h2,l2,h3,l3,h4,l4,h5,l5,h6,l6,h7,l7;
    split_bf(a.x,h0,l0); split_bf(a.y,h1,l1); split_bf(a.z,h2,l2); split_bf(a.w,h3,l3);
    split_bf(b.x,h4,l4); split_bf(b.y,h5,l5); split_bf(b.z,h6,l6); split_bf(b.w,h7,l7);
    bf162 hh01(h0,h1), hh23(h2,h3), hh45(h4,h5), hh67(h6,h7);
    bf162 ll01(l0,l1), ll23(l2,l3), ll45(l4,l5), ll67(l6,l7);
    h = make_uint4(*(uint32_t*)&hh01, *(uint32_t*)&hh23, *(uint32_t*)&hh45, *(uint32_t*)&hh67);
    l = make_uint4(*(uint32_t*)&ll01, *(uint32_t*)&ll23, *(uint32_t*)&ll45, *(uint32_t*)&ll67);
}

// ---------------------------------------------------------------------------
// W [k][n] -> [n][k] transpose + hi/lo split.  block (32,8), grid (16,16,4)
// ---------------------------------------------------------------------------
__global__ __launch_bounds__(256) void convert_w_kernel(
    const float* __restrict__ Wq, const float* __restrict__ Wk,
    const float* __restrict__ Wv, const float* __restrict__ W0)
{
    __shared__ float tile[32][33];
    int z = blockIdx.z;
    const float* W = (z == 0) ? Wq : (z == 1 ? Wk : (z == 2 ? Wv : W0));
    int k0 = blockIdx.x * 32, n0 = blockIdx.y * 32;
    int tx = threadIdx.x, ty = threadIdx.y;
    #pragma unroll
    for (int it = 0; it < 4; it++)
        tile[ty + it * 8][tx] = W[(size_t)(k0 + ty + it * 8) * D_ + n0 + tx];
    __syncthreads();
    size_t zb = (size_t)z * (512*512);
    #pragma unroll
    for (int it = 0; it < 4; it++) {
        int nr = ty + it * 8;
        bf16 hi, lo;
        split_bf(tile[tx][nr], hi, lo);
        g_Whi[zb + (size_t)(n0 + nr) * D_ + k0 + tx] = hi;
        g_Wlo[zb + (size_t)(n0 + nr) * D_ + k0 + tx] = lo;
    }
}

// ---------------------------------------------------------------------------
// 3xBF16 tensor-core GEMM, templated M and N tile.
//   MT/NT : CTA tile (MT in {64,128}, NT in {64,128})
//   HEADSPLIT : head-split output; runtime vt selects bf16 V output
//   AFP32 : A read as fp32 and hi/lo-split in registers
// K = 512, 16 stages of 32, double-buffered, ldmatrix fragments.
// ---------------------------------------------------------------------------
#define SA 40

constexpr int gemm_smem_b(int mt, int nt) {
    return 2 * (2 * mt * SA + 2 * nt * SA) * 2;
}

template<int MT, int NT, bool HEADSPLIT, bool AFP32>
__device__ __forceinline__ void gemm_core(
    const float* __restrict__ Af_g,
    const bf16* __restrict__ Ahi_g, const bf16* __restrict__ Alo_g,
    const bf16* __restrict__ Bhi_g, const bf16* __restrict__ Blo_g,
    const float* __restrict__ bias, float* __restrict__ Y, bool vt)
{
    constexpr int WM = MT / 32;            // M warps
    constexpr int WN = 8 / WM;             // N warps
    constexpr int NTILES = (NT / WN) / 8;  // 8-wide j tiles per warp
    constexpr int NB = NTILES / 2;
    constexpr int A_HT = MT * SA;
    constexpr int B_HT = NT * SA;
    constexpr int BUF_H = 2 * A_HT + 2 * B_HT;
    constexpr int TPRA = 256 / MT;         // threads per A row
    constexpr int KPA = 32 / TPRA;         // halves per thread along k
    constexpr int APT = KPA / 8;           // uint4 per side (A)
    constexpr int TPRB = 256 / NT;
    constexpr int BPT = NT / 64;

    extern __shared__ __align__(16) bf16 smh[];
    const int tid = threadIdx.x;
    const int lane = tid & 31, wid = tid >> 5;
    const int g = lane >> 2, t4 = lane & 3;
    const int warp_m = (wid % WM) * 32;
    const int warp_n = (wid / WM) * (NT / WN);
    const int m0 = blockIdx.x * MT, n0 = blockIdx.y * NT;

    const int am = tid / TPRA, ahh = (tid % TPRA) * KPA;
    const int bn = tid / TPRB, bo = (tid % TPRB) * (32 / TPRB);

    const float* Af = Af_g ? Af_g + (size_t)(m0 + am) * D_ + ahh : (const float*)0;
    const bf16* Ash = Ahi_g ? Ahi_g + (size_t)(m0 + am) * D_ + ahh : (const bf16*)0;
    const bf16* Asl = Alo_g ? Alo_g + (size_t)(m0 + am) * D_ + ahh : (const bf16*)0;
    const bf16* Bsh = Bhi_g + (size_t)(n0 + bn) * D_ + bo;
    const bf16* Bsl = Blo_g + (size_t)(n0 + bn) * D_ + bo;

    float acc[2][NTILES][4];
    #pragma unroll
    for (int i = 0; i < 2; i++)
        #pragma unroll
        for (int j = 0; j < NTILES; j++)
            #pragma unroll
            for (int c = 0; c < 4; c++) acc[i][j][c] = 0.0f;

    const int lrow = lane & 15;
    const int lk   = (lane >> 4) * 8;
    const int bln  = lane & 7;
    const int bseg = (lane >> 3) & 1;
    const int bhi16 = (lane >> 4);
    const uint32_t smem_base = smem_u32(smh);
    const uint32_t aoff0 = ((warp_m + lrow)      * SA + lk) * 2;
    const uint32_t aoff1 = ((warp_m + 16 + lrow) * SA + lk) * 2;
    uint32_t boffs[NB];
    #pragma unroll
    for (int t = 0; t < NB; t++)
        boffs[t] = ((warp_n + t * 16 + bln) * SA + bseg * 8) * 2 + bhi16 * (8 * SA * 2);

    float4 rAf[APT * 2];
    uint4 rA_h[APT], rA_l[APT];
    uint4 rB_h[BPT], rB_l[BPT];

    if (AFP32) {
        #pragma unroll
        for (int u = 0; u < APT * 2; u++) rAf[u] = *(const float4*)(Af + u * 4);
    } else {
        #pragma unroll
        for (int p = 0; p < APT; p++) {
            rA_h[p] = *(const uint4*)(Ash + p * 8);
            rA_l[p] = *(const uint4*)(Asl + p * 8);
        }
    }
    #pragma unroll
    for (int p = 0; p < BPT; p++) {
        rB_h[p] = *(const uint4*)(Bsh + p * 8);
        rB_l[p] = *(const uint4*)(Bsl + p * 8);
    }

    for (int s = 0; s < 16; s++) {
        const int buf = s & 1;
        bf16* Ah_s = smh + buf * BUF_H;
        bf16* Al_s = Ah_s + A_HT;
        bf16* Bh_s = Al_s + A_HT;
        bf16* Bl_s = Bh_s + B_HT;

        if (AFP32) {
            #pragma unroll
            for (int p = 0; p < APT; p++) {
                uint4 h, l;
                pack8(rAf[2 * p], rAf[2 * p + 1], h, l);
                *(uint4*)&Ah_s[am * SA + ahh + p * 8] = h;
                *(uint4*)&Al_s[am * SA + ahh + p * 8] = l;
            }
        } else {
            #pragma unroll
            for (int p = 0; p < APT; p++) {
                *(uint4*)&Ah_s[am * SA + ahh + p * 8] = rA_h[p];
                *(uint4*)&Al_s[am * SA + ahh + p * 8] = rA_l[p];
            }
        }
        #pragma unroll
        for (int p = 0; p < BPT; p++) {
            *(uint4*)&Bh_s[bn * SA + bo + p * 8] = rB_h[p];
            *(uint4*)&Bl_s[bn * SA + bo + p * 8] = rB_l[p];
        }
        __syncthreads();

        if (s < 15) {
            const int off = (s + 1) * 32;
            if (AFP32) {
                #pragma unroll
                for (int u = 0; u < APT * 2; u++) rAf[u] = *(const float4*)(Af + off + u * 4);
            } else {
                #pragma unroll
                for (int p = 0; p < APT; p++) {
                    rA_h[p] = *(const uint4*)(Ash + off + p * 8);
                    rA_l[p] = *(const uint4*)(Asl + off + p * 8);
                }
            }
            #pragma unroll
            for (int p = 0; p < BPT; p++) {
                rB_h[p] = *(const uint4*)(Bsh + off + p * 8);
                rB_l[p] = *(const uint4*)(Bsl + off + p * 8);
            }
        }

        const uint32_t base = smem_base + (uint32_t)(buf * BUF_H * 2);
        const uint32_t aBh = base;
        const uint32_t aBl = base + A_HT * 2;
        const uint32_t bBh = base + 2 * A_HT * 2;
        const uint32_t bBl = bBh + B_HT * 2;

        #pragma unroll
        for (int kk = 0; kk < 2; kk++) {
            const uint32_t ko = kk * 32;
            uint32_t Ah0[4], Ah1[4], Al0[4], Al1[4];
            uint32_t Bh[NB][4], Bl[NB][4];
            ldm_x4(Ah0, aBh + aoff0 + ko);
            ldm_x4(Ah1, aBh + aoff1 + ko);
            ldm_x4(Al0, aBl + aoff0 + ko);
            ldm_x4(Al1, aBl + aoff1 + ko);
            #pragma unroll
            for (int t = 0; t < NB; t++) {
                ldm_x4(Bh[t], bBh + boffs[t] + ko);
                ldm_x4(Bl[t], bBl + boffs[t] + ko);
            }

            #pragma unroll
            for (int i = 0; i < 2; i++) {
                uint32_t* ahp = i ? Ah1 : Ah0;
                uint32_t* alp = i ? Al1 : Al0;
                #pragma unroll
                for (int j = 0; j < NTILES; j++) {
                    uint32_t* bhp = Bh[j >> 1];
                    uint32_t* blp = Bl[j >> 1];
                    uint32_t bhf[2] = { bhp[(j & 1) * 2], bhp[(j & 1) * 2 + 1] };
                    uint32_t blf[2] = { blp[(j & 1) * 2], blp[(j & 1) * 2 + 1] };
                    mma_bf16(acc[i][j], ahp, bhf);
                    mma_bf16(acc[i][j], ahp, blf);
                    mma_bf16(acc[i][j], alp, bhf);
                }
            }
        }
    }

    #pragma unroll
    for (int i = 0; i < 2; i++) {
        #pragma unroll
        for (int j = 0; j < NTILES; j++) {
            int col_loc = warp_n + (j >> 1) * 16 + (j & 1) * 8 + 2 * t4;
            int cng = n0 + col_loc;
            float b0 = bias[cng], b1 = bias[cng + 1];
            int r0 = m0 + warp_m + i * 16 + g;
            int r1 = r0 + 8;
            float2 v0 = make_float2(acc[i][j][0] + b0, acc[i][j][1] + b1);
            float2 v1 = make_float2(acc[i][j][2] + b0, acc[i][j][3] + b1);
            if (HEADSPLIT) {
                int h = cng >> 6, dk = cng & 63;
                size_t a0 = ((size_t)((r0 >> 8) * H_ + h) * L_ + (r0 & 255)) * DK_ + dk;
                size_t a1 = ((size_t)((r1 >> 8) * H_ + h) * L_ + (r1 & 255)) * DK_ + dk;
                if (vt) {
                    // V output: bf16 hi/lo, natural [bh][j][dk] layout (coalesced 4B)
                    bf16 ha, la, hb, lb;
                    split_bf(v0.x, ha, la); split_bf(v0.y, hb, lb);
                    *(bf162*)&g_Vhi[a0] = bf162(ha, hb);
                    *(bf162*)&g_Vlo[a0] = bf162(la, lb);
                    split_bf(v1.x, ha, la); split_bf(v1.y, hb, lb);
                    *(bf162*)&g_Vhi[a1] = bf162(ha, hb);
                    *(bf162*)&g_Vlo[a1] = bf162(la, lb);
                } else {
                    *(float2*)(Y + a0) = v0;
                    *(float2*)(Y + a1) = v1;
                }
            } else {
                *(float2*)(Y + (size_t)r0 * D_ + cng) = v0;
                *(float2*)(Y + (size_t)r1 * D_ + cng) = v1;
            }
        }
    }
}

// QKV: MT=128, NT=128, fused fp32 split. grid (8, 4, 3) = 96 CTAs (one wave).
__global__ __launch_bounds__(256) void qkv_mma_kernel(
    const float* __restrict__ q, const float* __restrict__ k, const float* __restrict__ v,
    const float* __restrict__ bq, const float* __restrict__ bk, const float* __restrict__ bv)
{
    int z = blockIdx.z;
    const float* X    = (z == 0) ? q  : (z == 1 ? k  : v);
    const float* bias = (z == 0) ? bq : (z == 1 ? bk : bv);
    float* out        = (z == 0) ? g_qh : (z == 1 ? g_kh : nullptr);
    gemm_core<128, 128, true, true>(X, nullptr, nullptr,
                                    g_Whi + (size_t)z * (512*512), g_Wlo + (size_t)z * (512*512),
                                    bias, out, z == 2);
}

// Output projection: MT=64, NT=64. grid (16, 8) = 128 CTAs.
__global__ __launch_bounds__(256, 2) void out_mma_kernel(
    const float* __restrict__ b0, float* __restrict__ Y)
{
    gemm_core<64, 64, false, false>(nullptr, g_ctx_hi, g_ctx_lo,
                                    g_Whi + (size_t)3 * (512*512), g_Wlo + (size_t)3 * (512*512),
                                    b0, Y, false);
}

// ---------------------------------------------------------------------------
// Scores: grid (8, 4, 32) = 1024 CTAs, 256 thr, smem ~26KB.
// ---------------------------------------------------------------------------
#define SCQ_ST 34
#define SCK_ST 68

__global__ __launch_bounds__(256) void scores_kernel(
    const int* __restrict__ mask, const float* __restrict__ vp)
{
    __shared__ float Qs[64 * SCQ_ST];
    __shared__ float Ks[64 * SCK_ST];
    __shared__ float vps[64];

    const int tid = threadIdx.x;
    const int bh = blockIdx.z;
    const int b = bh >> 3, h = bh & 7;
    const int i0 = blockIdx.x * 32, j0 = blockIdx.y * 64;
    const int jb = blockIdx.y;

    const float* qh = g_qh + (size_t)(bh * L_ + i0) * DK_;
    const float* kh = g_kh + (size_t)(bh * L_ + j0) * DK_;

    if (tid < 64) vps[tid] = vp[h * DK_ + tid];
    {
        int r = tid >> 3, d0 = (tid & 7) * 8;
        float4 t0 = *(const float4*)&qh[(size_t)r * DK_ + d0];
        float4 t1 = *(const float4*)&qh[(size_t)r * DK_ + d0 + 4];
        Qs[(d0 + 0) * SCQ_ST + r] = t0.x; Qs[(d0 + 1) * SCQ_ST + r] = t0.y;
        Qs[(d0 + 2) * SCQ_ST + r] = t0.z; Qs[(d0 + 3) * SCQ_ST + r] = t0.w;
        Qs[(d0 + 4) * SCQ_ST + r] = t1.x; Qs[(d0 + 5) * SCQ_ST + r] = t1.y;
        Qs[(d0 + 6) * SCQ_ST + r] = t1.z; Qs[(d0 + 7) * SCQ_ST + r] = t1.w;
    }
    {
        int r = tid >> 2, d0 = (tid & 3) * 16;
        #pragma unroll
        for (int u = 0; u < 4; u++) {
            float4 t = *(const float4*)&kh[(size_t)r * DK_ + d0 + u * 4];
            Ks[(d0 + u * 4 + 0) * SCK_ST + r] = t.x;
            Ks[(d0 + u * 4 + 1) * SCK_ST + r] = t.y;
            Ks[(d0 + u * 4 + 2) * SCK_ST + r] = t.z;
            Ks[(d0 + u * 4 + 3) * SCK_ST + r] = t.w;
        }
    }
    __syncthreads();

    const int il2 = tid >> 4;
    const int jg  = tid & 15;

    float acc[2][4] = {};
    #pragma unroll 2
    for (int d = 0; d < 64; d++) {
        float w = vps[d];
        float2 qv = *(const float2*)&Qs[d * SCQ_ST + il2 * 2];
        float4 kv = *(const float4*)&Ks[d * SCK_ST + jg * 4];
        float qa[2] = {qv.x, qv.y};
        float kb[4] = {kv.x, kv.y, kv.z, kv.w};
        #pragma unroll
        for (int a = 0; a < 2; a++)
            #pragma unroll
            for (int c = 0; c < 4; c++)
                acc[a][c] += w * tanh_fast(qa[a] + kb[c]);
    }

    float rpart[2];
    #pragma unroll
    for (int a = 0; a < 2; a++) {
        int row = i0 + il2 * 2 + a;
        const int4 m = *(const int4*)(mask + ((size_t)b * L_ + row) * L_ + j0 + jg * 4);
        float e0 = m.x ? __expf(acc[a][0]) : 0.0f;
        float e1 = m.y ? __expf(acc[a][1]) : 0.0f;
        float e2 = m.z ? __expf(acc[a][2]) : 0.0f;
        float e3 = m.w ? __expf(acc[a][3]) : 0.0f;
        rpart[a] = (e0 + e1) + (e2 + e3);
        bf16 h0, l0, h1, l1, h2, l2, h3, l3;
        split_bf(e0, h0, l0); split_bf(e1, h1, l1);
        split_bf(e2, h2, l2); split_bf(e3, h3, l3);
        size_t off = (size_t)bh * (L_ * L_) + (size_t)row * L_ + j0 + jg * 4;
        bf162* ph = (bf162*)&g_Ehi[off];
        bf162* pl = (bf162*)&g_Elo[off];
        ph[0] = bf162(h0, h1); ph[1] = bf162(h2, h3);
        pl[0] = bf162(l0, l1); pl[1] = bf162(l2, l3);
    }
    #pragma unroll
    for (int a = 0; a < 2; a++) {
        #pragma unroll
        for (int off = 8; off > 0; off >>= 1)
            rpart[a] += __shfl_xor_sync(0xFFFFFFFFu, rpart[a], off);
    }
    if (jg == 0) {
        int row = i0 + il2 * 2;
        float* dst = g_rsum4 + ((size_t)(bh * 4 + jb)) * L_ + row;
        dst[0] = rpart[0];
        dst[1] = rpart[1];
    }
}

// ---------------------------------------------------------------------------
// PV via tensor cores, M-tile 64: grid (4, 32) = 128 CTAs, 256 thr.
// B loaded from natural-layout V [bh][j][dk] bf16 with ldmatrix.trans.
// ctx[i][dk] = (1/rowsum) * sum_j E[i][j] * V[j][dk].  K=256, 8 stages of 32.
// Warps: 2(M) x 4(N); warp tile 32x16.
// ---------------------------------------------------------------------------
#define PVA_H (64*SA)
#define PVV_ST 72
#define PVV_H (32*PVV_ST)
#define PVBUF_H (2*PVA_H + 2*PVV_H)
#define PV_SMEM_BYTES (2*PVBUF_H*2)

__global__ __launch_bounds__(256, 2) void pv_mma_kernel()
{
    extern __shared__ __align__(16) bf16 smh[];
    const int tid = threadIdx.x;
    const int lane = tid & 31, wid = tid >> 5;
    const int g = lane >> 2, t4 = lane & 3;
    const int warp_m = (wid & 1) * 32;
    const int warp_n = (wid >> 1) * 16;
    const int m0 = blockIdx.x * 64;
    const int bhz = blockIdx.y;
    const int b = bhz >> 3, h = bhz & 7;

    const bf16* Ahi_g = g_Ehi + (size_t)bhz * (L_ * L_);
    const bf16* Alo_g = g_Elo + (size_t)bhz * (L_ * L_);
    const bf16* Vhi_g = g_Vhi + (size_t)bhz * (L_ * DK_);
    const bf16* Vlo_g = g_Vlo + (size_t)bhz * (L_ * DK_);

    // A (E) loader: 64 rows x 32 k-halves per stage
    const int am = tid >> 2, ao = (tid & 3) * 8;
    const bf16* Asrc_h = Ahi_g + (size_t)(m0 + am) * L_ + ao;
    const bf16* Asrc_l = Alo_g + (size_t)(m0 + am) * L_ + ao;
    // V loader: 32 j rows x 64 dk per stage (natural layout)
    const int vjr = tid >> 3, vseg = (tid & 7) * 8;
    const bf16* Vsrc_h = Vhi_g + (size_t)vjr * DK_ + vseg;
    const bf16* Vsrc_l = Vlo_g + (size_t)vjr * DK_ + vseg;

    float acc[2][2][4];
    #pragma unroll
    for (int i = 0; i < 2; i++)
        #pragma unroll
        for (int j = 0; j < 2; j++)
            #pragma unroll
            for (int c = 0; c < 4; c++) acc[i][j][c] = 0.0f;

    const int lrow = lane & 15;
    const int lk   = (lane >> 4) * 8;
    const uint32_t smem_base = smem_u32(smh);
    const uint32_t aoff0 = ((warp_m + lrow)      * SA + lk) * 2;
    const uint32_t aoff1 = ((warp_m + 16 + lrow) * SA + lk) * 2;
    // trans fragment address: j row (within 16-chunk) + dk column
    const int vln = (lane & 7) + ((lane >> 3) & 1) * 8;
    const uint32_t boffT = ((uint32_t)vln * PVV_ST + warp_n + (lane >> 4) * 8) * 2;

    uint4 rAh, rAl, rVh, rVl;
    rAh = *(const uint4*)(Asrc_h);
    rAl = *(const uint4*)(Asrc_l);
    rVh = *(const uint4*)(Vsrc_h);
    rVl = *(const uint4*)(Vsrc_l);

    for (int s = 0; s < 8; s++) {
        const int buf = s & 1;
        bf16* Ah_s = smh + buf * PVBUF_H;
        bf16* Al_s = Ah_s + PVA_H;
        bf16* Vh_s = Al_s + PVA_H;
        bf16* Vl_s = Vh_s + PVV_H;

        *(uint4*)&Ah_s[am * SA + ao] = rAh;
        *(uint4*)&Al_s[am * SA + ao] = rAl;
        *(uint4*)&Vh_s[vjr * PVV_ST + vseg] = rVh;
        *(uint4*)&Vl_s[vjr * PVV_ST + vseg] = rVl;
        __syncthreads();

        if (s < 7) {
            const int aoffg = (s + 1) * 32;              // E k advance (halves)
            const size_t voffg = (size_t)(s + 1) * 32 * DK_;  // V j advance
            rAh = *(const uint4*)(Asrc_h + aoffg);
            rAl = *(const uint4*)(Asrc_l + aoffg);
            rVh = *(const uint4*)(Vsrc_h + voffg);
            rVl = *(const uint4*)(Vsrc_l + voffg);
        }

        const uint32_t base = smem_base + (uint32_t)(buf * PVBUF_H * 2);
        const uint32_t aBh = base;
        const uint32_t aBl = base + PVA_H * 2;
        const uint32_t vBh = base + 2 * PVA_H * 2;
        const uint32_t vBl = vBh + PVV_H * 2;

        #pragma unroll
        for (int kk = 0; kk < 2; kk++) {
            const uint32_t koA = kk * 32;                  // 16 halves
            const uint32_t koV = kk * 16 * PVV_ST * 2;     // 16 j rows
            uint32_t Ah0[4], Ah1[4], Al0[4], Al1[4];
            uint32_t Bh0[4], Bl0[4];
            ldm_x4(Ah0, aBh + aoff0 + koA);
            ldm_x4(Ah1, aBh + aoff1 + koA);
            ldm_x4(Al0, aBl + aoff0 + koA);
            ldm_x4(Al1, aBl + aoff1 + koA);
            ldm_x4_t(Bh0, vBh + boffT + koV);
            ldm_x4_t(Bl0, vBl + boffT + koV);

            #pragma unroll
            for (int i = 0; i < 2; i++) {
                uint32_t* ahp = i ? Ah1 : Ah0;
                uint32_t* alp = i ? Al1 : Al0;
                #pragma unroll
                for (int j = 0; j < 2; j++) {
                    uint32_t bhf[2] = { Bh0[j * 2], Bh0[j * 2 + 1] };
                    uint32_t blf[2] = { Bl0[j * 2], Bl0[j * 2 + 1] };
                    mma_bf16(acc[i][j], ahp, bhf);
                    mma_bf16(acc[i][j], ahp, blf);
                    mma_bf16(acc[i][j], alp, bhf);
                }
            }
        }
    }

    const float* rs = g_rsum4 + (size_t)(bhz * 4) * L_;
    #pragma unroll
    for (int i = 0; i < 2; i++) {
        #pragma unroll
        for (int j = 0; j < 2; j++) {
            int col_loc = warp_n + j * 8 + 2 * t4;
            int r0 = m0 + warp_m + i * 16 + g;
            int r1 = r0 + 8;
            float inv0 = 1.0f / ((rs[r0] + rs[L_ + r0]) + (rs[2 * L_ + r0] + rs[3 * L_ + r0]));
            float inv1 = 1.0f / ((rs[r1] + rs[L_ + r1]) + (rs[2 * L_ + r1] + rs[3 * L_ + r1]));
            float v00 = acc[i][j][0] * inv0, v01 = acc[i][j][1] * inv0;
            float v10 = acc[i][j][2] * inv1, v11 = acc[i][j][3] * inv1;
            bf16 ha, la, hb, lb;
            size_t o0 = ((size_t)(b * L_ + r0)) * D_ + h * DK_ + col_loc;
            size_t o1 = ((size_t)(b * L_ + r1)) * D_ + h * DK_ + col_loc;
            split_bf(v00, ha, la); split_bf(v01, hb, lb);
            *(bf162*)&g_ctx_hi[o0] = bf162(ha, hb);
            *(bf162*)&g_ctx_lo[o0] = bf162(la, lb);
            split_bf(v10, ha, la); split_bf(v11, hb, lb);
            *(bf162*)&g_ctx_hi[o1] = bf162(ha, hb);
            *(bf162*)&g_ctx_lo[o1] = bf162(la, lb);
        }
    }
}

// ===========================================================================
extern "C" void kernel_launch(void* const* d_in, const int* in_sizes, int n_in,
                              void* d_out, int out_size)
{
    const float* q    = (const float*)d_in[0];
    const float* k    = (const float*)d_in[1];
    const float* v    = (const float*)d_in[2];
    const int*   mask = (const int*)  d_in[3];
    const float* Wq   = (const float*)d_in[4];
    const float* bq   = (const float*)d_in[5];
    const float* Wk   = (const float*)d_in[6];
    const float* bk   = (const float*)d_in[7];
    const float* Wv   = (const float*)d_in[8];
    const float* bv   = (const float*)d_in[9];
    const float* vp   = (const float*)d_in[10];
    const float* W0   = (const float*)d_in[11];
    const float* b0   = (const float*)d_in[12];
    float* out = (float*)d_out;

    static bool attr_set = false;
    if (!attr_set) {
        cudaFuncSetAttribute(qkv_mma_kernel,
                             cudaFuncAttributeMaxDynamicSharedMemorySize, gemm_smem_b(128, 128));
        cudaFuncSetAttribute(out_mma_kernel,
                             cudaFuncAttributeMaxDynamicSharedMemorySize, gemm_smem_b(64, 64));
        cudaFuncSetAttribute(pv_mma_kernel,
                             cudaFuncAttributeMaxDynamicSharedMemorySize, PV_SMEM_BYTES);
        attr_set = true;
    }

    convert_w_kernel<<<dim3(16, 16, 4), dim3(32, 8)>>>(Wq, Wk, Wv, W0);
    qkv_mma_kernel<<<dim3(8, 4, 3), 256, gemm_smem_b(128, 128)>>>(q, k, v, bq, bk, bv);
    scores_kernel<<<dim3(8, 4, 32), 256>>>(mask, vp);
    pv_mma_kernel<<<dim3(4, 32), 256, PV_SMEM_BYTES>>>();
    out_mma_kernel<<<dim3(16, 8), 256, gemm_smem_b(64, 64)>>>(b0, out);
}